// round 2
// baseline (speedup 1.0000x reference)
#include <cuda_runtime.h>
#include <math.h>

// ---------------- problem constants ----------------
#define DIM   4096
#define NH    32
#define NKV   8
#define HD    128
#define B_    2
#define S_    2048
#define M_    (B_*S_)          // 4096 rows

// ---------------- scratch (static device globals; no allocs allowed) -------
__device__ float g_q[(size_t)M_ * DIM];          // 64 MB
__device__ float g_k[(size_t)M_ * NKV * HD];     // 16 MB
__device__ float g_v[(size_t)M_ * NKV * HD];     // 16 MB
__device__ float g_att[(size_t)M_ * DIM];        // 64 MB

// ---------------- SGEMM: C[M,N] = A[M,K] @ B[K,N], all row-major -----------
#define BM 128
#define BN 128
#define BK 8

__global__ __launch_bounds__(256) void sgemm_kernel(
    const float* __restrict__ A, const float* __restrict__ B,
    float* __restrict__ C, int M, int N, int K)
{
    __shared__ float As[BK][BM];   // transposed A tile
    __shared__ float Bs[BK][BN];

    const int bx = blockIdx.x * BN;
    const int by = blockIdx.y * BM;
    const int tid = threadIdx.x;
    const int tx = tid & 15;
    const int ty = tid >> 4;

    // global-load assignments (exact tiling: M,N,K all divisible)
    const int aRow = tid >> 1;            // 0..127
    const int aCol = (tid & 1) * 4;       // 0 or 4
    const int bRow = tid >> 5;            // 0..7
    const int bCol = (tid & 31) * 4;      // 0..124

    float acc[8][8];
#pragma unroll
    for (int i = 0; i < 8; i++)
#pragma unroll
        for (int j = 0; j < 8; j++) acc[i][j] = 0.f;

    const float* Ag = A + (size_t)(by + aRow) * K + aCol;
    const float* Bg = B + (size_t)bRow * N + bx + bCol;

    for (int k0 = 0; k0 < K; k0 += BK) {
        float4 a4 = *(const float4*)(Ag + k0);
        As[aCol + 0][aRow] = a4.x;
        As[aCol + 1][aRow] = a4.y;
        As[aCol + 2][aRow] = a4.z;
        As[aCol + 3][aRow] = a4.w;
        float4 b4 = *(const float4*)(Bg + (size_t)k0 * N);
        *(float4*)&Bs[bRow][bCol] = b4;
        __syncthreads();

#pragma unroll
        for (int k = 0; k < BK; k++) {
            float4 a0 = *(const float4*)&As[k][ty * 8];
            float4 a1 = *(const float4*)&As[k][ty * 8 + 4];
            float4 b0 = *(const float4*)&Bs[k][tx * 8];
            float4 b1 = *(const float4*)&Bs[k][tx * 8 + 4];
            float ar[8] = {a0.x, a0.y, a0.z, a0.w, a1.x, a1.y, a1.z, a1.w};
            float br[8] = {b0.x, b0.y, b0.z, b0.w, b1.x, b1.y, b1.z, b1.w};
#pragma unroll
            for (int i = 0; i < 8; i++)
#pragma unroll
                for (int j = 0; j < 8; j++)
                    acc[i][j] += ar[i] * br[j];
        }
        __syncthreads();
    }

#pragma unroll
    for (int i = 0; i < 8; i++) {
        float* Cp = C + (size_t)(by + ty * 8 + i) * N + bx + tx * 8;
        *(float4*)Cp       = make_float4(acc[i][0], acc[i][1], acc[i][2], acc[i][3]);
        *(float4*)(Cp + 4) = make_float4(acc[i][4], acc[i][5], acc[i][6], acc[i][7]);
    }
}

// ---------------- RoPE (in place, q and k in one launch) --------------------
__global__ void rope_kernel(float* __restrict__ q, float* __restrict__ k,
                            const int* __restrict__ start_pos)
{
    const long long qp = (long long)M_ * NH  * (HD / 2);
    const long long kp = (long long)M_ * NKV * (HD / 2);
    long long idx = (long long)blockIdx.x * blockDim.x + threadIdx.x;
    if (idx >= qp + kp) return;

    float* t;
    int nheads;
    if (idx < qp) { t = q; nheads = NH; }
    else          { t = k; nheads = NKV; idx -= qp; }

    const int ppr = nheads * (HD / 2);          // pairs per row
    const int row = (int)(idx / ppr);
    const int pr  = (int)(idx % ppr);
    const int h   = pr / (HD / 2);
    const int i   = pr % (HD / 2);
    const int s   = row % S_;

    const float pos  = (float)(s + start_pos[0]);
    const float ex   = (float)(2 * i) * (1.0f / (float)HD);
    const float freq = powf(10000.0f, -ex);     // accurate pow
    const float ang  = pos * freq;
    float sn, cs;
    sincosf(ang, &sn, &cs);

    float* p = t + (size_t)row * nheads * HD + (size_t)h * HD + 2 * i;
    const float tr = p[0];
    const float ti = p[1];
    p[0] = tr * cs - ti * sn;
    p[1] = tr * sn + ti * cs;
}

// ---------------- flash attention (fp32, causal, GQA) ----------------------
#define BR 64
#define BC 64
#define QSTR 132      // padded row stride (floats), keeps float4 alignment
#define PSTR 68       // P stored transposed: [BC][PSTR]
#define ATT_SMEM ((BR*QSTR + BC*QSTR + BC*QSTR + BC*PSTR) * 4)

__global__ __launch_bounds__(256) void attn_kernel(
    const float* __restrict__ Q, const float* __restrict__ K,
    const float* __restrict__ V, float* __restrict__ O)
{
    extern __shared__ float sm[];
    float* Qs = sm;                    // BR x QSTR
    float* Ks = Qs + BR * QSTR;        // BC x QSTR
    float* Vs = Ks + BC * QSTR;        // BC x QSTR
    float* Ps = Vs + BC * QSTR;        // BC x PSTR  (transposed: [col][row])

    const int qt = blockIdx.x;
    const int h  = blockIdx.y;
    const int b  = blockIdx.z;
    const int kvh = h >> 2;            // N_REP = 4
    const int tid = threadIdx.x;
    const int tx = tid & 15;
    const int ty = tid >> 4;
    const int q0 = qt * BR;

    // load Q tile (64 x 128)
    for (int i = tid; i < BR * (HD / 4); i += 256) {
        const int r  = i >> 5;             // 32 float4 per row
        const int c4 = (i & 31) * 4;
        float4 v = *(const float4*)(Q + (size_t)(b * S_ + q0 + r) * DIM + h * HD + c4);
        *(float4*)&Qs[r * QSTR + c4] = v;
    }

    float m[4], l[4], o[4][8];
#pragma unroll
    for (int i = 0; i < 4; i++) {
        m[i] = -1e30f; l[i] = 0.f;
#pragma unroll
        for (int j = 0; j < 8; j++) o[i][j] = 0.f;
    }
    const float scale = 0.08838834764831845f;   // 1/sqrt(128)

    for (int kt = 0; kt <= qt; kt++) {
        __syncthreads();   // protect Ks/Vs/Ps from previous iteration readers
        for (int i = tid; i < BC * (HD / 4); i += 256) {
            const int r  = i >> 5;
            const int c4 = (i & 31) * 4;
            const size_t g = (size_t)(b * S_ + kt * BC + r) * (NKV * HD) + kvh * HD + c4;
            *(float4*)&Ks[r * QSTR + c4] = *(const float4*)(K + g);
            *(float4*)&Vs[r * QSTR + c4] = *(const float4*)(V + g);
        }
        __syncthreads();

        // scores: 4x4 micro-tile, d vectorized by 4
        float s[4][4];
#pragma unroll
        for (int i = 0; i < 4; i++)
#pragma unroll
            for (int j = 0; j < 4; j++) s[i][j] = 0.f;

        for (int d = 0; d < HD; d += 4) {
            float4 aq[4], ak[4];
#pragma unroll
            for (int i = 0; i < 4; i++) aq[i] = *(const float4*)&Qs[(ty * 4 + i) * QSTR + d];
#pragma unroll
            for (int j = 0; j < 4; j++) ak[j] = *(const float4*)&Ks[(tx * 4 + j) * QSTR + d];
#pragma unroll
            for (int i = 0; i < 4; i++)
#pragma unroll
                for (int j = 0; j < 4; j++)
                    s[i][j] += aq[i].x * ak[j].x + aq[i].y * ak[j].y
                             + aq[i].z * ak[j].z + aq[i].w * ak[j].w;
        }

        // scale + causal mask (only diagonal tile can mask)
        const bool diag = (kt == qt);
#pragma unroll
        for (int i = 0; i < 4; i++)
#pragma unroll
            for (int j = 0; j < 4; j++) {
                float v = s[i][j] * scale;
                if (diag && (tx * 4 + j) > (ty * 4 + i)) v = -1e30f;
                s[i][j] = v;
            }

        // online softmax; row statistics reduced over the 16 tx lanes
#pragma unroll
        for (int i = 0; i < 4; i++) {
            float mt = fmaxf(fmaxf(s[i][0], s[i][1]), fmaxf(s[i][2], s[i][3]));
#pragma unroll
            for (int w = 8; w >= 1; w >>= 1)
                mt = fmaxf(mt, __shfl_xor_sync(0xffffffffu, mt, w));
            const float mn = fmaxf(m[i], mt);
            const float al = __expf(m[i] - mn);
            m[i] = mn;
            float rs = 0.f;
#pragma unroll
            for (int j = 0; j < 4; j++) {
                const float p = __expf(s[i][j] - mn);
                s[i][j] = p;
                rs += p;
            }
#pragma unroll
            for (int w = 8; w >= 1; w >>= 1)
                rs += __shfl_xor_sync(0xffffffffu, rs, w);
            l[i] = l[i] * al + rs;
#pragma unroll
            for (int j = 0; j < 8; j++) o[i][j] *= al;
#pragma unroll
            for (int j = 0; j < 4; j++)
                Ps[(tx * 4 + j) * PSTR + ty * 4 + i] = s[i][j];
        }
        __syncthreads();

        // O += P @ V  (thread covers rows ty*4..+4, cols tx*4..+4 and 64+tx*4..+4)
#pragma unroll 4
        for (int c = 0; c < BC; c++) {
            const float4 p4  = *(const float4*)&Ps[c * PSTR + ty * 4];
            const float4 vlo = *(const float4*)&Vs[c * QSTR + tx * 4];
            const float4 vhi = *(const float4*)&Vs[c * QSTR + 64 + tx * 4];
            const float pv[4] = {p4.x, p4.y, p4.z, p4.w};
#pragma unroll
            for (int i = 0; i < 4; i++) {
                o[i][0] += pv[i] * vlo.x;  o[i][1] += pv[i] * vlo.y;
                o[i][2] += pv[i] * vlo.z;  o[i][3] += pv[i] * vlo.w;
                o[i][4] += pv[i] * vhi.x;  o[i][5] += pv[i] * vhi.y;
                o[i][6] += pv[i] * vhi.z;  o[i][7] += pv[i] * vhi.w;
            }
        }
    }

    // epilogue: divide by l, write [b, s, h*128 + col] layout for the wo GEMM
#pragma unroll
    for (int i = 0; i < 4; i++) {
        const float inv = 1.0f / l[i];
        float* orow = O + (size_t)(b * S_ + q0 + ty * 4 + i) * DIM + h * HD;
        *(float4*)(orow + tx * 4)      = make_float4(o[i][0] * inv, o[i][1] * inv,
                                                     o[i][2] * inv, o[i][3] * inv);
        *(float4*)(orow + 64 + tx * 4) = make_float4(o[i][4] * inv, o[i][5] * inv,
                                                     o[i][6] * inv, o[i][7] * inv);
    }
}

// ---------------- launch ----------------------------------------------------
extern "C" void kernel_launch(void* const* d_in, const int* in_sizes, int n_in,
                              void* d_out, int out_size)
{
    const float* x  = (const float*)d_in[0];
    const float* wq = (const float*)d_in[1];
    const float* wk = (const float*)d_in[2];
    const float* wv = (const float*)d_in[3];
    const float* wo = (const float*)d_in[4];
    // d_in[5] = mask (pure causal triu of -1e9; applied analytically)
    const int* start_pos = (const int*)d_in[6];
    float* out = (float*)d_out;

    float *q, *k, *v, *att;
    cudaGetSymbolAddress((void**)&q,   g_q);
    cudaGetSymbolAddress((void**)&k,   g_k);
    cudaGetSymbolAddress((void**)&v,   g_v);
    cudaGetSymbolAddress((void**)&att, g_att);

    // QKV projections
    sgemm_kernel<<<dim3(DIM / BN, M_ / BM), 256>>>(x, wq, q, M_, DIM, DIM);
    sgemm_kernel<<<dim3((NKV * HD) / BN, M_ / BM), 256>>>(x, wk, k, M_, NKV * HD, DIM);
    sgemm_kernel<<<dim3((NKV * HD) / BN, M_ / BM), 256>>>(x, wv, v, M_, NKV * HD, DIM);

    // RoPE on q and k (single launch)
    {
        const long long pairs = (long long)M_ * (NH + NKV) * (HD / 2);
        rope_kernel<<<(unsigned)((pairs + 255) / 256), 256>>>(q, k, start_pos);
    }

    // attention
    cudaFuncSetAttribute(attn_kernel, cudaFuncAttributeMaxDynamicSharedMemorySize,
                         ATT_SMEM);
    attn_kernel<<<dim3(S_ / BR, NH, B_), 256, ATT_SMEM>>>(q, k, v, att);

    // output projection
    sgemm_kernel<<<dim3(DIM / BN, M_ / BM), 256>>>(att, wo, out, M_, DIM, DIM);
}

// round 3
// speedup vs baseline: 1.0028x; 1.0028x over previous
#include <cuda_runtime.h>
#include <math.h>

// ---------------- problem constants ----------------
#define DIM   4096
#define NH    32
#define NKV   8
#define HD    128
#define B_    2
#define S_    2048
#define M_    (B_*S_)          // 4096 rows

// ---------------- scratch (static device globals; no allocs allowed) -------
__device__ float g_q[(size_t)M_ * DIM];          // 64 MB
__device__ float g_k[(size_t)M_ * NKV * HD];     // 16 MB
__device__ float g_v[(size_t)M_ * NKV * HD];     // 16 MB
__device__ float g_att[(size_t)M_ * DIM];        // 64 MB

// ---------------- SGEMM: C[M,N] = A[M,K] @ B[K,N], all row-major -----------
#define BM 128
#define BN 128
#define BK 8

__global__ __launch_bounds__(256) void sgemm_kernel(
    const float* __restrict__ A, const float* __restrict__ B,
    float* __restrict__ C, int M, int N, int K)
{
    __shared__ float As[BK][BM];   // transposed A tile
    __shared__ float Bs[BK][BN];

    const int bx = blockIdx.x * BN;
    const int by = blockIdx.y * BM;
    const int tid = threadIdx.x;
    const int tx = tid & 15;
    const int ty = tid >> 4;

    // global-load assignments (exact tiling: M,N,K all divisible)
    const int aRow = tid >> 1;            // 0..127
    const int aCol = (tid & 1) * 4;       // 0 or 4
    const int bRow = tid >> 5;            // 0..7
    const int bCol = (tid & 31) * 4;      // 0..124

    float acc[8][8];
#pragma unroll
    for (int i = 0; i < 8; i++)
#pragma unroll
        for (int j = 0; j < 8; j++) acc[i][j] = 0.f;

    const float* Ag = A + (size_t)(by + aRow) * K + aCol;
    const float* Bg = B + (size_t)bRow * N + bx + bCol;

    for (int k0 = 0; k0 < K; k0 += BK) {
        float4 a4 = *(const float4*)(Ag + k0);
        As[aCol + 0][aRow] = a4.x;
        As[aCol + 1][aRow] = a4.y;
        As[aCol + 2][aRow] = a4.z;
        As[aCol + 3][aRow] = a4.w;
        float4 b4 = *(const float4*)(Bg + (size_t)k0 * N);
        *(float4*)&Bs[bRow][bCol] = b4;
        __syncthreads();

#pragma unroll
        for (int k = 0; k < BK; k++) {
            float4 a0 = *(const float4*)&As[k][ty * 8];
            float4 a1 = *(const float4*)&As[k][ty * 8 + 4];
            float4 b0 = *(const float4*)&Bs[k][tx * 8];
            float4 b1 = *(const float4*)&Bs[k][tx * 8 + 4];
            float ar[8] = {a0.x, a0.y, a0.z, a0.w, a1.x, a1.y, a1.z, a1.w};
            float br[8] = {b0.x, b0.y, b0.z, b0.w, b1.x, b1.y, b1.z, b1.w};
#pragma unroll
            for (int i = 0; i < 8; i++)
#pragma unroll
                for (int j = 0; j < 8; j++)
                    acc[i][j] += ar[i] * br[j];
        }
        __syncthreads();
    }

#pragma unroll
    for (int i = 0; i < 8; i++) {
        float* Cp = C + (size_t)(by + ty * 8 + i) * N + bx + tx * 8;
        *(float4*)Cp       = make_float4(acc[i][0], acc[i][1], acc[i][2], acc[i][3]);
        *(float4*)(Cp + 4) = make_float4(acc[i][4], acc[i][5], acc[i][6], acc[i][7]);
    }
}

// ---------------- RoPE (in place, q and k in one launch) --------------------
__global__ void rope_kernel(float* __restrict__ q, float* __restrict__ k,
                            const int* __restrict__ start_pos)
{
    const long long qp = (long long)M_ * NH  * (HD / 2);
    const long long kp = (long long)M_ * NKV * (HD / 2);
    long long idx = (long long)blockIdx.x * blockDim.x + threadIdx.x;
    if (idx >= qp + kp) return;

    float* t;
    int nheads;
    if (idx < qp) { t = q; nheads = NH; }
    else          { t = k; nheads = NKV; idx -= qp; }

    const int ppr = nheads * (HD / 2);          // pairs per row
    const int row = (int)(idx / ppr);
    const int pr  = (int)(idx % ppr);
    const int h   = pr / (HD / 2);
    const int i   = pr % (HD / 2);
    const int s   = row % S_;

    const float pos  = (float)(s + start_pos[0]);
    const float ex   = (float)(2 * i) * (1.0f / (float)HD);
    const float freq = powf(10000.0f, -ex);     // accurate pow
    const float ang  = pos * freq;
    float sn, cs;
    sincosf(ang, &sn, &cs);

    float* p = t + (size_t)row * nheads * HD + (size_t)h * HD + 2 * i;
    const float tr = p[0];
    const float ti = p[1];
    p[0] = tr * cs - ti * sn;
    p[1] = tr * sn + ti * cs;
}

// ---------------- flash attention (fp32, causal, GQA) ----------------------
#define BR 64
#define BC 64
#define QSTR 132      // padded row stride (floats), keeps float4 alignment
#define PSTR 68       // P stored transposed: [BC][PSTR]
#define ATT_SMEM ((BR*QSTR + BC*QSTR + BC*QSTR + BC*PSTR) * 4)

__global__ __launch_bounds__(256) void attn_kernel(
    const float* __restrict__ Q, const float* __restrict__ K,
    const float* __restrict__ V, float* __restrict__ O)
{
    extern __shared__ float sm[];
    float* Qs = sm;                    // BR x QSTR
    float* Ks = Qs + BR * QSTR;        // BC x QSTR
    float* Vs = Ks + BC * QSTR;        // BC x QSTR
    float* Ps = Vs + BC * QSTR;        // BC x PSTR  (transposed: [col][row])

    const int qt = blockIdx.x;
    const int h  = blockIdx.y;
    const int b  = blockIdx.z;
    const int kvh = h >> 2;            // N_REP = 4
    const int tid = threadIdx.x;
    const int tx = tid & 15;
    const int ty = tid >> 4;
    const int q0 = qt * BR;

    // load Q tile (64 x 128)
    for (int i = tid; i < BR * (HD / 4); i += 256) {
        const int r  = i >> 5;             // 32 float4 per row
        const int c4 = (i & 31) * 4;
        float4 v = *(const float4*)(Q + (size_t)(b * S_ + q0 + r) * DIM + h * HD + c4);
        *(float4*)&Qs[r * QSTR + c4] = v;
    }

    float m[4], l[4], o[4][8];
#pragma unroll
    for (int i = 0; i < 4; i++) {
        m[i] = -1e30f; l[i] = 0.f;
#pragma unroll
        for (int j = 0; j < 8; j++) o[i][j] = 0.f;
    }
    const float scale = 0.08838834764831845f;   // 1/sqrt(128)

    for (int kt = 0; kt <= qt; kt++) {
        __syncthreads();   // protect Ks/Vs/Ps from previous iteration readers
        for (int i = tid; i < BC * (HD / 4); i += 256) {
            const int r  = i >> 5;
            const int c4 = (i & 31) * 4;
            const size_t g = (size_t)(b * S_ + kt * BC + r) * (NKV * HD) + kvh * HD + c4;
            *(float4*)&Ks[r * QSTR + c4] = *(const float4*)(K + g);
            *(float4*)&Vs[r * QSTR + c4] = *(const float4*)(V + g);
        }
        __syncthreads();

        // scores: 4x4 micro-tile, d vectorized by 4
        float s[4][4];
#pragma unroll
        for (int i = 0; i < 4; i++)
#pragma unroll
            for (int j = 0; j < 4; j++) s[i][j] = 0.f;

        for (int d = 0; d < HD; d += 4) {
            float4 aq[4], ak[4];
#pragma unroll
            for (int i = 0; i < 4; i++) aq[i] = *(const float4*)&Qs[(ty * 4 + i) * QSTR + d];
#pragma unroll
            for (int j = 0; j < 4; j++) ak[j] = *(const float4*)&Ks[(tx * 4 + j) * QSTR + d];
#pragma unroll
            for (int i = 0; i < 4; i++)
#pragma unroll
                for (int j = 0; j < 4; j++)
                    s[i][j] += aq[i].x * ak[j].x + aq[i].y * ak[j].y
                             + aq[i].z * ak[j].z + aq[i].w * ak[j].w;
        }

        // scale + causal mask (only diagonal tile can mask)
        const bool diag = (kt == qt);
#pragma unroll
        for (int i = 0; i < 4; i++)
#pragma unroll
            for (int j = 0; j < 4; j++) {
                float v = s[i][j] * scale;
                if (diag && (tx * 4 + j) > (ty * 4 + i)) v = -1e30f;
                s[i][j] = v;
            }

        // online softmax; row statistics reduced over the 16 tx lanes
#pragma unroll
        for (int i = 0; i < 4; i++) {
            float mt = fmaxf(fmaxf(s[i][0], s[i][1]), fmaxf(s[i][2], s[i][3]));
#pragma unroll
            for (int w = 8; w >= 1; w >>= 1)
                mt = fmaxf(mt, __shfl_xor_sync(0xffffffffu, mt, w));
            const float mn = fmaxf(m[i], mt);
            const float al = __expf(m[i] - mn);
            m[i] = mn;
            float rs = 0.f;
#pragma unroll
            for (int j = 0; j < 4; j++) {
                const float p = __expf(s[i][j] - mn);
                s[i][j] = p;
                rs += p;
            }
#pragma unroll
            for (int w = 8; w >= 1; w >>= 1)
                rs += __shfl_xor_sync(0xffffffffu, rs, w);
            l[i] = l[i] * al + rs;
#pragma unroll
            for (int j = 0; j < 8; j++) o[i][j] *= al;
#pragma unroll
            for (int j = 0; j < 4; j++)
                Ps[(tx * 4 + j) * PSTR + ty * 4 + i] = s[i][j];
        }
        __syncthreads();

        // O += P @ V  (thread covers rows ty*4..+4, cols tx*4..+4 and 64+tx*4..+4)
#pragma unroll 4
        for (int c = 0; c < BC; c++) {
            const float4 p4  = *(const float4*)&Ps[c * PSTR + ty * 4];
            const float4 vlo = *(const float4*)&Vs[c * QSTR + tx * 4];
            const float4 vhi = *(const float4*)&Vs[c * QSTR + 64 + tx * 4];
            const float pv[4] = {p4.x, p4.y, p4.z, p4.w};
#pragma unroll
            for (int i = 0; i < 4; i++) {
                o[i][0] += pv[i] * vlo.x;  o[i][1] += pv[i] * vlo.y;
                o[i][2] += pv[i] * vlo.z;  o[i][3] += pv[i] * vlo.w;
                o[i][4] += pv[i] * vhi.x;  o[i][5] += pv[i] * vhi.y;
                o[i][6] += pv[i] * vhi.z;  o[i][7] += pv[i] * vhi.w;
            }
        }
    }

    // epilogue: divide by l, write [b, s, h*128 + col] layout for the wo GEMM
#pragma unroll
    for (int i = 0; i < 4; i++) {
        const float inv = 1.0f / l[i];
        float* orow = O + (size_t)(b * S_ + q0 + ty * 4 + i) * DIM + h * HD;
        *(float4*)(orow + tx * 4)      = make_float4(o[i][0] * inv, o[i][1] * inv,
                                                     o[i][2] * inv, o[i][3] * inv);
        *(float4*)(orow + 64 + tx * 4) = make_float4(o[i][4] * inv, o[i][5] * inv,
                                                     o[i][6] * inv, o[i][7] * inv);
    }
}

// ---------------- launch ----------------------------------------------------
extern "C" void kernel_launch(void* const* d_in, const int* in_sizes, int n_in,
                              void* d_out, int out_size)
{
    const float* x  = (const float*)d_in[0];
    const float* wq = (const float*)d_in[1];
    const float* wk = (const float*)d_in[2];
    const float* wv = (const float*)d_in[3];
    const float* wo = (const float*)d_in[4];
    // d_in[5] = mask (pure causal triu of -1e9; applied analytically)
    const int* start_pos = (const int*)d_in[6];
    float* out = (float*)d_out;

    float *q, *k, *v, *att;
    cudaGetSymbolAddress((void**)&q,   g_q);
    cudaGetSymbolAddress((void**)&k,   g_k);
    cudaGetSymbolAddress((void**)&v,   g_v);
    cudaGetSymbolAddress((void**)&att, g_att);

    // QKV projections
    sgemm_kernel<<<dim3(DIM / BN, M_ / BM), 256>>>(x, wq, q, M_, DIM, DIM);
    sgemm_kernel<<<dim3((NKV * HD) / BN, M_ / BM), 256>>>(x, wk, k, M_, NKV * HD, DIM);
    sgemm_kernel<<<dim3((NKV * HD) / BN, M_ / BM), 256>>>(x, wv, v, M_, NKV * HD, DIM);

    // RoPE on q and k (single launch)
    {
        const long long pairs = (long long)M_ * (NH + NKV) * (HD / 2);
        rope_kernel<<<(unsigned)((pairs + 255) / 256), 256>>>(q, k, start_pos);
    }

    // attention
    cudaFuncSetAttribute(attn_kernel, cudaFuncAttributeMaxDynamicSharedMemorySize,
                         ATT_SMEM);
    attn_kernel<<<dim3(S_ / BR, NH, B_), 256, ATT_SMEM>>>(q, k, v, att);

    // output projection
    sgemm_kernel<<<dim3(DIM / BN, M_ / BM), 256>>>(att, wo, out, M_, DIM, DIM);
}

// round 6
// speedup vs baseline: 1.3578x; 1.3540x over previous
#include <cuda_runtime.h>
#include <math.h>
#include <stdint.h>

// ---------------- problem constants ----------------
#define DIM   4096
#define NH    32
#define NKV   8
#define HD    128
#define B_    2
#define S_    2048
#define M_    (B_*S_)          // 4096 rows

// ---------------- scratch (static device globals; no allocs allowed) -------
__device__ float g_q[(size_t)M_ * DIM];          // 64 MB
__device__ float g_k[(size_t)M_ * NKV * HD];     // 16 MB
__device__ float g_v[(size_t)M_ * NKV * HD];     // 16 MB
__device__ float g_att[(size_t)M_ * DIM];        // 64 MB

// =====================================================================
// TF32 tensor-core GEMM with 3xTF32 error compensation.
// C[M,N] = A[M,K] @ B[K,N], all row-major. M%128==0, N%128==0, K%32==0.
// CTA tile 128x128x32, 8 warps (2x4), warp tile 64x32.
// =====================================================================
#define GBM 128
#define GBN 128
#define GBK 32
#define AST 36    // As row stride (floats): bank = 4*row+col -> conflict free
#define BST 136   // Bs row stride: bank = 8*k+n -> conflict free

__device__ __forceinline__ uint32_t f2tf32(float x) {
    uint32_t r;
    asm("cvt.rna.tf32.f32 %0, %1;" : "=r"(r) : "f"(x));
    return r;
}

__device__ __forceinline__ void mma_tf32(float c[4], uint32_t a0, uint32_t a1,
                                         uint32_t a2, uint32_t a3,
                                         uint32_t b0, uint32_t b1) {
    asm volatile(
        "mma.sync.aligned.m16n8k8.row.col.f32.tf32.tf32.f32 "
        "{%0,%1,%2,%3}, {%4,%5,%6,%7}, {%8,%9}, {%0,%1,%2,%3};"
        : "+f"(c[0]), "+f"(c[1]), "+f"(c[2]), "+f"(c[3])
        : "r"(a0), "r"(a1), "r"(a2), "r"(a3), "r"(b0), "r"(b1));
}

// dynamic smem layout (uint32 units)
#define SM_AH 0
#define SM_AL (GBM * AST)
#define SM_BH (2 * GBM * AST)
#define SM_BL (2 * GBM * AST + GBK * BST)
#define GEMM_SMEM ((2 * GBM * AST + 2 * GBK * BST) * 4)

__global__ __launch_bounds__(256, 1) void tf32_gemm_kernel(
    const float* __restrict__ A, const float* __restrict__ B,
    float* __restrict__ C, int M, int N, int K)
{
    extern __shared__ uint32_t smu[];
    uint32_t* AsH = smu + SM_AH;
    uint32_t* AsL = smu + SM_AL;
    uint32_t* BsH = smu + SM_BH;
    uint32_t* BsL = smu + SM_BL;

    const int tid  = threadIdx.x;
    const int wid  = tid >> 5;
    const int lane = tid & 31;
    const int wm   = wid >> 2;        // 0..1  -> 64-row slab
    const int wn   = wid & 3;         // 0..3  -> 32-col slab
    const int gid  = lane >> 2;       // group id 0..7
    const int tig  = lane & 3;        // thread-in-group 0..3

    const int by = blockIdx.y * GBM;
    const int bx = blockIdx.x * GBN;

    // global-load assignments:
    // A tile: 128 rows x 32 cols. thread -> 4 x float4.
    const int aR = tid >> 3;          // 0..31 (+32 per iter)
    const int aC = (tid & 7) * 4;     // 0..28
    // B tile: 32 rows x 128 cols. thread -> 4 x float4.
    const int bR = tid >> 5;          // 0..7 (+8 per iter)
    const int bC = (tid & 31) * 4;    // 0..124

    float acc[4][4][4];
#pragma unroll
    for (int i = 0; i < 4; i++)
#pragma unroll
        for (int j = 0; j < 4; j++)
#pragma unroll
            for (int t = 0; t < 4; t++) acc[i][j][t] = 0.f;

    const int nk = K / GBK;
    float4 pa[4], pb[4];

    // prefetch tile 0
#pragma unroll
    for (int it = 0; it < 4; it++) {
        pa[it] = *(const float4*)(A + (size_t)(by + aR + it * 32) * K + aC);
        pb[it] = *(const float4*)(B + (size_t)(bR + it * 8) * N + bx + bC);
    }

    for (int kb = 0; kb < nk; kb++) {
        __syncthreads();
        // store staged tile to smem with tf32 hi/lo split
#pragma unroll
        for (int it = 0; it < 4; it++) {
            const float va[4] = {pa[it].x, pa[it].y, pa[it].z, pa[it].w};
            const int am = aR + it * 32;
#pragma unroll
            for (int e = 0; e < 4; e++) {
                const uint32_t hi = f2tf32(va[e]);
                const float lo = va[e] - __uint_as_float(hi);
                AsH[am * AST + aC + e] = hi;
                AsL[am * AST + aC + e] = f2tf32(lo);
            }
            const float vb[4] = {pb[it].x, pb[it].y, pb[it].z, pb[it].w};
            const int bk = bR + it * 8;
#pragma unroll
            for (int e = 0; e < 4; e++) {
                const uint32_t hi = f2tf32(vb[e]);
                const float lo = vb[e] - __uint_as_float(hi);
                BsH[bk * BST + bC + e] = hi;
                BsL[bk * BST + bC + e] = f2tf32(lo);
            }
        }
        __syncthreads();

        // issue global loads for next tile (overlap with MMA work)
        if (kb + 1 < nk) {
            const int k0 = (kb + 1) * GBK;
#pragma unroll
            for (int it = 0; it < 4; it++) {
                pa[it] = *(const float4*)(A + (size_t)(by + aR + it * 32) * K + k0 + aC);
                pb[it] = *(const float4*)(B + (size_t)(k0 + bR + it * 8) * N + bx + bC);
            }
        }

        // compute: 4 k-steps of 8
#pragma unroll
        for (int ks = 0; ks < 4; ks++) {
            const int kk = ks * 8;
            // PTX m16n8k8 A-fragment order:
            //   a0:(row=g,   col=t)   a1:(row=g+8, col=t)
            //   a2:(row=g,   col=t+4) a3:(row=g+8, col=t+4)
            uint32_t ah[4][4], al[4][4];     // [m-tile][a0..a3]
#pragma unroll
            for (int mt = 0; mt < 4; mt++) {
                const int r0 = wm * 64 + mt * 16 + gid;
                ah[mt][0] = AsH[r0 * AST + kk + tig];
                ah[mt][1] = AsH[(r0 + 8) * AST + kk + tig];
                ah[mt][2] = AsH[r0 * AST + kk + tig + 4];
                ah[mt][3] = AsH[(r0 + 8) * AST + kk + tig + 4];
                al[mt][0] = AsL[r0 * AST + kk + tig];
                al[mt][1] = AsL[(r0 + 8) * AST + kk + tig];
                al[mt][2] = AsL[r0 * AST + kk + tig + 4];
                al[mt][3] = AsL[(r0 + 8) * AST + kk + tig + 4];
            }
            // B-fragment order: b0:(k=t, n=g)  b1:(k=t+4, n=g)
            uint32_t bh[4][2], bl[4][2];     // [n-tile][b0..b1]
#pragma unroll
            for (int nt = 0; nt < 4; nt++) {
                const int c0 = wn * 32 + nt * 8 + gid;
                bh[nt][0] = BsH[(kk + tig) * BST + c0];
                bh[nt][1] = BsH[(kk + tig + 4) * BST + c0];
                bl[nt][0] = BsL[(kk + tig) * BST + c0];
                bl[nt][1] = BsL[(kk + tig + 4) * BST + c0];
            }
#pragma unroll
            for (int mt = 0; mt < 4; mt++)
#pragma unroll
                for (int nt = 0; nt < 4; nt++) {
                    mma_tf32(acc[mt][nt], ah[mt][0], ah[mt][1], ah[mt][2], ah[mt][3],
                             bh[nt][0], bh[nt][1]);
                    mma_tf32(acc[mt][nt], ah[mt][0], ah[mt][1], ah[mt][2], ah[mt][3],
                             bl[nt][0], bl[nt][1]);
                    mma_tf32(acc[mt][nt], al[mt][0], al[mt][1], al[mt][2], al[mt][3],
                             bh[nt][0], bh[nt][1]);
                }
        }
    }

    // epilogue: c0,c1 -> (row=g, col=2t..2t+1); c2,c3 -> (row=g+8, same cols)
#pragma unroll
    for (int mt = 0; mt < 4; mt++) {
        const int r0 = by + wm * 64 + mt * 16 + gid;
#pragma unroll
        for (int nt = 0; nt < 4; nt++) {
            const int c0 = bx + wn * 32 + nt * 8 + tig * 2;
            *(float2*)(C + (size_t)r0 * N + c0) =
                make_float2(acc[mt][nt][0], acc[mt][nt][1]);
            *(float2*)(C + (size_t)(r0 + 8) * N + c0) =
                make_float2(acc[mt][nt][2], acc[mt][nt][3]);
        }
    }
}

// ---------------- RoPE (in place, q and k in one launch) --------------------
__global__ void rope_kernel(float* __restrict__ q, float* __restrict__ k,
                            const int* __restrict__ start_pos)
{
    const long long qp = (long long)M_ * NH  * (HD / 2);
    const long long kp = (long long)M_ * NKV * (HD / 2);
    long long idx = (long long)blockIdx.x * blockDim.x + threadIdx.x;
    if (idx >= qp + kp) return;

    float* t;
    int nheads;
    if (idx < qp) { t = q; nheads = NH; }
    else          { t = k; nheads = NKV; idx -= qp; }

    const int ppr = nheads * (HD / 2);          // pairs per row
    const int row = (int)(idx / ppr);
    const int pr  = (int)(idx % ppr);
    const int h   = pr / (HD / 2);
    const int i   = pr % (HD / 2);
    const int s   = row % S_;

    const float pos  = (float)(s + start_pos[0]);
    const float ex   = (float)(2 * i) * (1.0f / (float)HD);
    const float freq = powf(10000.0f, -ex);     // accurate pow
    const float ang  = pos * freq;
    float sn, cs;
    sincosf(ang, &sn, &cs);

    float* p = t + (size_t)row * nheads * HD + (size_t)h * HD + 2 * i;
    const float tr = p[0];
    const float ti = p[1];
    p[0] = tr * cs - ti * sn;
    p[1] = tr * sn + ti * cs;
}

// ---------------- flash attention (fp32, causal, GQA) ----------------------
#define BR 64
#define BC 64
#define QSTR 132      // padded row stride (floats), keeps float4 alignment
#define PSTR 68       // P stored transposed: [BC][PSTR]
#define ATT_SMEM ((BR*QSTR + BC*QSTR + BC*QSTR + BC*PSTR) * 4)

__global__ __launch_bounds__(256) void attn_kernel(
    const float* __restrict__ Q, const float* __restrict__ K,
    const float* __restrict__ V, float* __restrict__ O)
{
    extern __shared__ float sm[];
    float* Qs = sm;                    // BR x QSTR
    float* Ks = Qs + BR * QSTR;        // BC x QSTR
    float* Vs = Ks + BC * QSTR;        // BC x QSTR
    float* Ps = Vs + BC * QSTR;        // BC x PSTR  (transposed: [col][row])

    const int qt = blockIdx.x;
    const int h  = blockIdx.y;
    const int b  = blockIdx.z;
    const int kvh = h >> 2;            // N_REP = 4
    const int tid = threadIdx.x;
    const int tx = tid & 15;
    const int ty = tid >> 4;
    const int q0 = qt * BR;

    // load Q tile (64 x 128)
    for (int i = tid; i < BR * (HD / 4); i += 256) {
        const int r  = i >> 5;             // 32 float4 per row
        const int c4 = (i & 31) * 4;
        float4 v = *(const float4*)(Q + (size_t)(b * S_ + q0 + r) * DIM + h * HD + c4);
        *(float4*)&Qs[r * QSTR + c4] = v;
    }

    float m[4], l[4], o[4][8];
#pragma unroll
    for (int i = 0; i < 4; i++) {
        m[i] = -1e30f; l[i] = 0.f;
#pragma unroll
        for (int j = 0; j < 8; j++) o[i][j] = 0.f;
    }
    const float scale = 0.08838834764831845f;   // 1/sqrt(128)

    for (int kt = 0; kt <= qt; kt++) {
        __syncthreads();   // protect Ks/Vs/Ps from previous iteration readers
        for (int i = tid; i < BC * (HD / 4); i += 256) {
            const int r  = i >> 5;
            const int c4 = (i & 31) * 4;
            const size_t g = (size_t)(b * S_ + kt * BC + r) * (NKV * HD) + kvh * HD + c4;
            *(float4*)&Ks[r * QSTR + c4] = *(const float4*)(K + g);
            *(float4*)&Vs[r * QSTR + c4] = *(const float4*)(V + g);
        }
        __syncthreads();

        // scores: 4x4 micro-tile, d vectorized by 4
        float s[4][4];
#pragma unroll
        for (int i = 0; i < 4; i++)
#pragma unroll
            for (int j = 0; j < 4; j++) s[i][j] = 0.f;

        for (int d = 0; d < HD; d += 4) {
            float4 aq[4], ak[4];
#pragma unroll
            for (int i = 0; i < 4; i++) aq[i] = *(const float4*)&Qs[(ty * 4 + i) * QSTR + d];
#pragma unroll
            for (int j = 0; j < 4; j++) ak[j] = *(const float4*)&Ks[(tx * 4 + j) * QSTR + d];
#pragma unroll
            for (int i = 0; i < 4; i++)
#pragma unroll
                for (int j = 0; j < 4; j++)
                    s[i][j] += aq[i].x * ak[j].x + aq[i].y * ak[j].y
                             + aq[i].z * ak[j].z + aq[i].w * ak[j].w;
        }

        // scale + causal mask (only diagonal tile can mask)
        const bool diag = (kt == qt);
#pragma unroll
        for (int i = 0; i < 4; i++)
#pragma unroll
            for (int j = 0; j < 4; j++) {
                float v = s[i][j] * scale;
                if (diag && (tx * 4 + j) > (ty * 4 + i)) v = -1e30f;
                s[i][j] = v;
            }

        // online softmax; row statistics reduced over the 16 tx lanes
#pragma unroll
        for (int i = 0; i < 4; i++) {
            float mt = fmaxf(fmaxf(s[i][0], s[i][1]), fmaxf(s[i][2], s[i][3]));
#pragma unroll
            for (int w = 8; w >= 1; w >>= 1)
                mt = fmaxf(mt, __shfl_xor_sync(0xffffffffu, mt, w));
            const float mn = fmaxf(m[i], mt);
            const float al = __expf(m[i] - mn);
            m[i] = mn;
            float rs = 0.f;
#pragma unroll
            for (int j = 0; j < 4; j++) {
                const float p = __expf(s[i][j] - mn);
                s[i][j] = p;
                rs += p;
            }
#pragma unroll
            for (int w = 8; w >= 1; w >>= 1)
                rs += __shfl_xor_sync(0xffffffffu, rs, w);
            l[i] = l[i] * al + rs;
#pragma unroll
            for (int j = 0; j < 8; j++) o[i][j] *= al;
#pragma unroll
            for (int j = 0; j < 4; j++)
                Ps[(tx * 4 + j) * PSTR + ty * 4 + i] = s[i][j];
        }
        __syncthreads();

        // O += P @ V  (thread covers rows ty*4..+4, cols tx*4..+4 and 64+tx*4..+4)
#pragma unroll 4
        for (int c = 0; c < BC; c++) {
            const float4 p4  = *(const float4*)&Ps[c * PSTR + ty * 4];
            const float4 vlo = *(const float4*)&Vs[c * QSTR + tx * 4];
            const float4 vhi = *(const float4*)&Vs[c * QSTR + 64 + tx * 4];
            const float pv[4] = {p4.x, p4.y, p4.z, p4.w};
#pragma unroll
            for (int i = 0; i < 4; i++) {
                o[i][0] += pv[i] * vlo.x;  o[i][1] += pv[i] * vlo.y;
                o[i][2] += pv[i] * vlo.z;  o[i][3] += pv[i] * vlo.w;
                o[i][4] += pv[i] * vhi.x;  o[i][5] += pv[i] * vhi.y;
                o[i][6] += pv[i] * vhi.z;  o[i][7] += pv[i] * vhi.w;
            }
        }
    }

    // epilogue: divide by l, write [b, s, h*128 + col] layout for the wo GEMM
#pragma unroll
    for (int i = 0; i < 4; i++) {
        const float inv = 1.0f / l[i];
        float* orow = O + (size_t)(b * S_ + q0 + ty * 4 + i) * DIM + h * HD;
        *(float4*)(orow + tx * 4)      = make_float4(o[i][0] * inv, o[i][1] * inv,
                                                     o[i][2] * inv, o[i][3] * inv);
        *(float4*)(orow + 64 + tx * 4) = make_float4(o[i][4] * inv, o[i][5] * inv,
                                                     o[i][6] * inv, o[i][7] * inv);
    }
}

// ---------------- launch ----------------------------------------------------
extern "C" void kernel_launch(void* const* d_in, const int* in_sizes, int n_in,
                              void* d_out, int out_size)
{
    const float* x  = (const float*)d_in[0];
    const float* wq = (const float*)d_in[1];
    const float* wk = (const float*)d_in[2];
    const float* wv = (const float*)d_in[3];
    const float* wo = (const float*)d_in[4];
    // d_in[5] = mask (pure causal triu of -1e9; applied analytically)
    const int* start_pos = (const int*)d_in[6];
    float* out = (float*)d_out;

    float *q, *k, *v, *att;
    cudaGetSymbolAddress((void**)&q,   g_q);
    cudaGetSymbolAddress((void**)&k,   g_k);
    cudaGetSymbolAddress((void**)&v,   g_v);
    cudaGetSymbolAddress((void**)&att, g_att);

    cudaFuncSetAttribute(tf32_gemm_kernel,
                         cudaFuncAttributeMaxDynamicSharedMemorySize, GEMM_SMEM);

    // QKV projections (tensor-core tf32 x3)
    tf32_gemm_kernel<<<dim3(DIM / GBN, M_ / GBM), 256, GEMM_SMEM>>>(
        x, wq, q, M_, DIM, DIM);
    tf32_gemm_kernel<<<dim3((NKV * HD) / GBN, M_ / GBM), 256, GEMM_SMEM>>>(
        x, wk, k, M_, NKV * HD, DIM);
    tf32_gemm_kernel<<<dim3((NKV * HD) / GBN, M_ / GBM), 256, GEMM_SMEM>>>(
        x, wv, v, M_, NKV * HD, DIM);

    // RoPE on q and k (single launch)
    {
        const long long pairs = (long long)M_ * (NH + NKV) * (HD / 2);
        rope_kernel<<<(unsigned)((pairs + 255) / 256), 256>>>(q, k, start_pos);
    }

    // attention
    cudaFuncSetAttribute(attn_kernel, cudaFuncAttributeMaxDynamicSharedMemorySize,
                         ATT_SMEM);
    attn_kernel<<<dim3(S_ / BR, NH, B_), 256, ATT_SMEM>>>(q, k, v, att);

    // output projection
    tf32_gemm_kernel<<<dim3(DIM / GBN, M_ / GBM), 256, GEMM_SMEM>>>(
        att, wo, out, M_, DIM, DIM);
}